// round 8
// baseline (speedup 1.0000x reference)
#include <cuda_runtime.h>

#define D   33
#define DD  (33 * 33)
#define NL  (33 * 33 * 33)   // 35937
#define NBASIS 8

#define QMAXF  2097151.0f    // 2^21 - 1  (stage-1 pair records)
#define Q11F   2047.0f       // 2^11 - 1  (stage-2 R,G)
#define Q10F   1023.0f       // 2^10 - 1  (stage-2 B)
#define BIASF  8388608.0f    // 2^23
#define EXPB   0x4B000000u   // float bits of 2^23

// stage-1: r-pair records, 6 x 21-bit in 16B  (.x = R0|G0<<21|B0<<42, .y = r+1)
// stage-2: single corner per 4B word, R:11 | G:11<<11 | B:10<<22 (copied to smem)
__device__ ulonglong2 g_pack1[NL];
__device__ unsigned   g_s2[NL];

// ---------------------------------------------------------------------------
// Helpers
// ---------------------------------------------------------------------------
__device__ __forceinline__ unsigned long long q21(float v) {
    v = fminf(fmaxf(v, 0.f), 1.f);
    return (unsigned long long)(v * QMAXF + 0.5f);
}
__device__ __forceinline__ unsigned qw3(float r, float g, float b) {
    r = fminf(fmaxf(r, 0.f), 1.f);
    g = fminf(fmaxf(g, 0.f), 1.f);
    b = fminf(fmaxf(b, 0.f), 1.f);
    unsigned R = (unsigned)(r * Q11F + 0.5f);
    unsigned G = (unsigned)(g * Q11F + 0.5f);
    unsigned B = (unsigned)(b * Q10F + 0.5f);
    return R | (G << 11) | (B << 22);
}

__device__ __forceinline__ void softmax8(const float* __restrict__ lc, float* w) {
    float m = -1e30f;
    #pragma unroll
    for (int n = 0; n < NBASIS; n++) m = fmaxf(m, __ldg(lc + n));
    float sum = 0.f;
    #pragma unroll
    for (int n = 0; n < NBASIS; n++) { w[n] = __expf(__ldg(lc + n) - m); sum += w[n]; }
    float inv = 1.0f / sum;
    #pragma unroll
    for (int n = 0; n < NBASIS; n++) w[n] *= inv;
}

__device__ __forceinline__ void combine8(const float* __restrict__ lut, int stage,
                                         int i, const float* w, float* acc) {
    acc[0] = acc[1] = acc[2] = 0.f;
    #pragma unroll
    for (int n = 0; n < NBASIS; n++) {
        const float* basep = lut + (((size_t)stage * NBASIS + n) * 3) * NL + i;
        #pragma unroll
        for (int c = 0; c < 3; c++)
            acc[c] = fmaf(w[n], __ldg(basep + (size_t)c * NL), acc[c]);
    }
}

// ---------------------------------------------------------------------------
// Kernel 1 (fused build+pack): softmax-combine basis LUTs and emit both
// packed formats directly. Each thread handles one grid entry; it recomputes
// the r+1 neighbor's stage-1 combine for the pair record (cheap, L1-hot).
// ---------------------------------------------------------------------------
__global__ void build_pack_kernel(const float* __restrict__ lut,
                                  const float* __restrict__ lc0,
                                  const float* __restrict__ lc1) {
    int idx = blockIdx.x * blockDim.x + threadIdx.x;
    if (idx >= NL) return;
    int ir = idx % D;

    float w0[NBASIS], w1[NBASIS];
    softmax8(lc0, w0);
    softmax8(lc1, w1);

    // stage-1 pair record
    float c0[3];
    combine8(lut, 0, idx, w0, c0);
    unsigned long long u0 = 0, u1 = 0;
    if (ir < D - 1) {
        float c1[3];
        combine8(lut, 0, idx + 1, w0, c1);
        u0 = q21(c0[0]) | (q21(c0[1]) << 21) | (q21(c0[2]) << 42);
        u1 = q21(c1[0]) | (q21(c1[1]) << 21) | (q21(c1[2]) << 42);
    }
    g_pack1[idx] = make_ulonglong2(u0, u1);

    // stage-2 single-corner word
    float c2[3];
    combine8(lut, 1, idx, w1, c2);
    g_s2[idx] = qw3(c2[0], c2[1], c2[2]);
}

// ---------------------------------------------------------------------------
// Decoders (exponent-OR -> biased floats; bias cancels in lerp differences)
// ---------------------------------------------------------------------------
__device__ __forceinline__ void dec3(unsigned long long u,
                                     float& x, float& y, float& z) {
    x = __uint_as_float(EXPB | (unsigned)(u & 0x1FFFFFull));
    y = __uint_as_float(EXPB | (unsigned)((u >> 21) & 0x1FFFFFull));
    z = __uint_as_float(EXPB | (unsigned)(u >> 42));
}
__device__ __forceinline__ void decq(unsigned w,
                                     float& R, float& G, float& B) {
    R = __uint_as_float(EXPB | (w & 0x7FFu));
    G = __uint_as_float(EXPB | ((w >> 11) & 0x7FFu));
    B = __uint_as_float(EXPB | (w >> 22));
}

__device__ __forceinline__ void coords(float r, float g, float b,
                                       int& idx, float& fr, float& fg, float& fb) {
    r = fminf(fmaxf(r, 0.f), 1.f) * (float)(D - 1);
    g = fminf(fmaxf(g, 0.f), 1.f) * (float)(D - 1);
    b = fminf(fmaxf(b, 0.f), 1.f) * (float)(D - 1);
    int ir = min((int)r, D - 2);
    int ig = min((int)g, D - 2);
    int ib = min((int)b, D - 2);
    fr = r - (float)ir;
    fg = g - (float)ig;
    fb = b - (float)ib;
    idx = ib * DD + ig * D + ir;
}

// Stage 1: 21-bit pair records from global, 4 x LDG.128.
__device__ __forceinline__ float3 lut3d_s1(float r, float g, float b) {
    int idx; float fr, fg, fb;
    coords(r, g, b, idx, fr, fg, fb);

    ulonglong2 u00 = __ldg(g_pack1 + idx);
    ulonglong2 u01 = __ldg(g_pack1 + idx + D);
    ulonglong2 u10 = __ldg(g_pack1 + idx + DD);
    ulonglong2 u11 = __ldg(g_pack1 + idx + DD + D);

    float R0, G0, B0, R1, G1, B1;

    dec3(u00.x, R0, G0, B0); dec3(u00.y, R1, G1, B1);
    float a00x = fmaf(fr, R1 - R0, R0);
    float a00y = fmaf(fr, G1 - G0, G0);
    float a00z = fmaf(fr, B1 - B0, B0);
    dec3(u01.x, R0, G0, B0); dec3(u01.y, R1, G1, B1);
    float a01x = fmaf(fr, R1 - R0, R0);
    float a01y = fmaf(fr, G1 - G0, G0);
    float a01z = fmaf(fr, B1 - B0, B0);
    dec3(u10.x, R0, G0, B0); dec3(u10.y, R1, G1, B1);
    float a10x = fmaf(fr, R1 - R0, R0);
    float a10y = fmaf(fr, G1 - G0, G0);
    float a10z = fmaf(fr, B1 - B0, B0);
    dec3(u11.x, R0, G0, B0); dec3(u11.y, R1, G1, B1);
    float a11x = fmaf(fr, R1 - R0, R0);
    float a11y = fmaf(fr, G1 - G0, G0);
    float a11z = fmaf(fr, B1 - B0, B0);

    float b0x = fmaf(fg, a01x - a00x, a00x);
    float b0y = fmaf(fg, a01y - a00y, a00y);
    float b0z = fmaf(fg, a01z - a00z, a00z);
    float b1x = fmaf(fg, a11x - a10x, a10x);
    float b1y = fmaf(fg, a11y - a10y, a10y);
    float b1z = fmaf(fg, a11z - a10z, a10z);

    float tx = fmaf(fb, b1x - b0x, b0x);
    float ty = fmaf(fb, b1y - b0y, b0y);
    float tz = fmaf(fb, b1z - b0z, b0z);

    const float sc = 1.0f / QMAXF;
    return make_float3((tx - BIASF) * sc, (ty - BIASF) * sc, (tz - BIASF) * sc);
}

// Stage 2: single-corner words from SHARED memory, 8 x LDS.32
// (random-lane LDS ~4 bank-conflict wavefronts vs ~28 line-wavefronts for LDG).
__device__ __forceinline__ float3 lut3d_s2(const unsigned* __restrict__ s2,
                                           float r, float g, float b) {
    int idx; float fr, fg, fb;
    coords(r, g, b, idx, fr, fg, fb);

    unsigned w000 = s2[idx];
    unsigned w001 = s2[idx + 1];
    unsigned w010 = s2[idx + D];
    unsigned w011 = s2[idx + D + 1];
    unsigned w100 = s2[idx + DD];
    unsigned w101 = s2[idx + DD + 1];
    unsigned w110 = s2[idx + DD + D];
    unsigned w111 = s2[idx + DD + D + 1];

    float R0, G0, B0, R1, G1, B1;

    decq(w000, R0, G0, B0); decq(w001, R1, G1, B1);
    float a00x = fmaf(fr, R1 - R0, R0);
    float a00y = fmaf(fr, G1 - G0, G0);
    float a00z = fmaf(fr, B1 - B0, B0);
    decq(w010, R0, G0, B0); decq(w011, R1, G1, B1);
    float a01x = fmaf(fr, R1 - R0, R0);
    float a01y = fmaf(fr, G1 - G0, G0);
    float a01z = fmaf(fr, B1 - B0, B0);
    decq(w100, R0, G0, B0); decq(w101, R1, G1, B1);
    float a10x = fmaf(fr, R1 - R0, R0);
    float a10y = fmaf(fr, G1 - G0, G0);
    float a10z = fmaf(fr, B1 - B0, B0);
    decq(w110, R0, G0, B0); decq(w111, R1, G1, B1);
    float a11x = fmaf(fr, R1 - R0, R0);
    float a11y = fmaf(fr, G1 - G0, G0);
    float a11z = fmaf(fr, B1 - B0, B0);

    float b0x = fmaf(fg, a01x - a00x, a00x);
    float b0y = fmaf(fg, a01y - a00y, a00y);
    float b0z = fmaf(fg, a01z - a00z, a00z);
    float b1x = fmaf(fg, a11x - a10x, a10x);
    float b1y = fmaf(fg, a11y - a10y, a10y);
    float b1z = fmaf(fg, a11z - a10z, a10z);

    float tx = fmaf(fb, b1x - b0x, b0x);
    float ty = fmaf(fb, b1y - b0y, b0y);
    float tz = fmaf(fb, b1z - b0z, b0z);

    return make_float3((tx - BIASF) * (1.0f / Q11F),
                       (ty - BIASF) * (1.0f / Q11F),
                       (tz - BIASF) * (1.0f / Q10F));
}

// ---------------------------------------------------------------------------
// Kernel 2: persistent fused dual-LUT apply.
// 1 block/SM (144KB smem table), 512 threads, grid-stride over pixel chunks.
// ---------------------------------------------------------------------------
#define APPLY_THREADS 512
#define PIX_PER_THREAD 4
#define CHUNK (APPLY_THREADS * PIX_PER_THREAD)   // 2048 px
#define S2_BYTES (NL * 4)

__global__ __launch_bounds__(APPLY_THREADS, 1)
void apply_lut_kernel(const float* __restrict__ gt,
                      float* __restrict__ out, int hw) {
    extern __shared__ unsigned s2[];

    // load stage-2 table into smem (vectorized: 35936 = 8984*4, + 1 tail word)
    {
        const uint4* src = reinterpret_cast<const uint4*>(g_s2);
        uint4* dst = reinterpret_cast<uint4*>(s2);
        for (int i = threadIdx.x; i < NL / 4; i += APPLY_THREADS)
            dst[i] = __ldg(src + i);
        if (threadIdx.x == 0) s2[NL - 1] = g_s2[NL - 1];
    }
    __syncthreads();

    const int nchunks = hw / CHUNK;   // 4050 exactly for 8294400

    for (int c = blockIdx.x; c < nchunks; c += gridDim.x) {
        int base = c * CHUNK + threadIdx.x * PIX_PER_THREAD;

        const float4 r4 = *reinterpret_cast<const float4*>(gt + base);
        const float4 g4 = *reinterpret_cast<const float4*>(gt + hw + base);
        const float4 b4 = *reinterpret_cast<const float4*>(gt + 2 * hw + base);

        float ri[4] = {r4.x, r4.y, r4.z, r4.w};
        float gi[4] = {g4.x, g4.y, g4.z, g4.w};
        float bi[4] = {b4.x, b4.y, b4.z, b4.w};
        float ro[4], go[4], bo[4];

        #pragma unroll
        for (int p = 0; p < PIX_PER_THREAD; p++) {
            float3 s = lut3d_s1(ri[p], gi[p], bi[p]);
            float3 f = lut3d_s2(s2, s.x, s.y, s.z);
            ro[p] = f.x; go[p] = f.y; bo[p] = f.z;
        }

        *reinterpret_cast<float4*>(out + base)          = make_float4(ro[0], ro[1], ro[2], ro[3]);
        *reinterpret_cast<float4*>(out + hw + base)     = make_float4(go[0], go[1], go[2], go[3]);
        *reinterpret_cast<float4*>(out + 2 * hw + base) = make_float4(bo[0], bo[1], bo[2], bo[3]);
    }
}

// ---------------------------------------------------------------------------
extern "C" void kernel_launch(void* const* d_in, const int* in_sizes, int n_in,
                              void* d_out, int out_size) {
    const float* gt  = (const float*)d_in[0];   // [3, 2160, 3840]
    const float* lut = (const float*)d_in[1];   // [2, 8, 3, 33, 33, 33]
    const float* lc0 = (const float*)d_in[2];   // [8]
    const float* lc1 = (const float*)d_in[3];   // [8]
    float* out = (float*)d_out;

    const int hw = in_sizes[0] / 3;             // 8294400

    static bool attr_set = false;
    if (!attr_set) {
        cudaFuncSetAttribute(apply_lut_kernel,
                             cudaFuncAttributeMaxDynamicSharedMemorySize, S2_BYTES);
        attr_set = true;
    }

    {
        int threads = 256;
        int blocks  = (NL + threads - 1) / threads;
        build_pack_kernel<<<blocks, threads>>>(lut, lc0, lc1);
    }
    {
        // persistent: ~1 block per SM (GB300 has 152 SMs); grid-stride loop
        apply_lut_kernel<<<152, APPLY_THREADS, S2_BYTES>>>(gt, out, hw);
    }
}

// round 9
// speedup vs baseline: 1.4097x; 1.4097x over previous
#include <cuda_runtime.h>

#define D   33
#define DD  (33 * 33)
#define NL  (33 * 33 * 33)   // 35937
#define NC  32               // cells per axis
#define NCELL (32 * 32 * 32) // 32768
#define NBASIS 8

#define Q16F   65535.0f      // stage-1 16-bit corners
#define Q11F   2047.0f       // stage-2 R,G
#define Q10F   1023.0f       // stage-2 B
#define BIASF  8388608.0f    // 2^23
#define EXPB   0x4B000000u   // float bits of 2^23

// fp32 combined LUTs (intermediate)
__device__ float4 g_clut[2][NL];
// stage-1: cell-indexed cube tables, 3 x uint4 per cell (R,G,B cubes; 8 x 16-bit corners each)
__device__ uint4  g_cube[NCELL * 3];
// stage-2: entry-indexed (r,g)-quad, 4 words of R:11|G:11<<11|B:10<<22
__device__ uint4  g_pack2[NL];

// ---------------------------------------------------------------------------
// Kernel 1: softmax-combine 8 basis LUTs (fp32), one thread per (stage,entry).
// ---------------------------------------------------------------------------
__global__ void build_clut_kernel(const float* __restrict__ lut,
                                  const float* __restrict__ lc0,
                                  const float* __restrict__ lc1) {
    int t = blockIdx.x * blockDim.x + threadIdx.x;
    if (t >= 2 * NL) return;
    int s = (t >= NL) ? 1 : 0;
    int i = t - s * NL;

    const float* lc = (s == 0) ? lc0 : lc1;
    float w[NBASIS];
    float m = -1e30f;
    #pragma unroll
    for (int n = 0; n < NBASIS; n++) m = fmaxf(m, __ldg(lc + n));
    float sum = 0.f;
    #pragma unroll
    for (int n = 0; n < NBASIS; n++) { w[n] = __expf(__ldg(lc + n) - m); sum += w[n]; }
    float inv = 1.0f / sum;

    float acc[3] = {0.f, 0.f, 0.f};
    #pragma unroll
    for (int n = 0; n < NBASIS; n++) {
        const float* basep = lut + (((size_t)s * NBASIS + n) * 3) * NL + i;
        float wn = w[n] * inv;
        #pragma unroll
        for (int c = 0; c < 3; c++)
            acc[c] = fmaf(wn, __ldg(basep + (size_t)c * NL), acc[c]);
    }
    g_clut[s][i] = make_float4(acc[0], acc[1], acc[2], 0.f);
}

// ---------------------------------------------------------------------------
// Kernel 2: pack both formats (one thread per LUT entry).
// ---------------------------------------------------------------------------
__device__ __forceinline__ unsigned q16(float v) {
    v = fminf(fmaxf(v, 0.f), 1.f);
    return (unsigned)(v * Q16F + 0.5f);
}
__device__ __forceinline__ unsigned qw3(float4 c) {
    float r = fminf(fmaxf(c.x, 0.f), 1.f);
    float g = fminf(fmaxf(c.y, 0.f), 1.f);
    float b = fminf(fmaxf(c.z, 0.f), 1.f);
    return (unsigned)(r * Q11F + 0.5f)
         | ((unsigned)(g * Q11F + 0.5f) << 11)
         | ((unsigned)(b * Q10F + 0.5f) << 22);
}

__global__ void pack_clut_kernel() {
    int idx = blockIdx.x * blockDim.x + threadIdx.x;
    if (idx >= NL) return;
    int ib  = idx / DD;
    int rem = idx - ib * DD;
    int ig  = rem / D;
    int ir  = rem - ig * D;

    // stage-2 quad (valid when ir<32 && ig<32, any ib)
    uint4 q = make_uint4(0, 0, 0, 0);
    if (ir < D - 1 && ig < D - 1) {
        q.x = qw3(g_clut[1][idx]);
        q.y = qw3(g_clut[1][idx + 1]);
        q.z = qw3(g_clut[1][idx + D]);
        q.w = qw3(g_clut[1][idx + D + 1]);
    }
    g_pack2[idx] = q;

    // stage-1 cube (valid cells: ir,ig,ib < 32)
    if (ir < D - 1 && ig < D - 1 && ib < D - 1) {
        // gather 8 corners, corner k = di + 2*dj + 4*dk
        float4 c[8];
        #pragma unroll
        for (int k = 0; k < 8; k++) {
            int off = (k & 1) + ((k >> 1) & 1) * D + ((k >> 2) & 1) * DD;
            c[k] = g_clut[0][idx + off];
        }
        int cidx = (ib * NC + ig) * NC + ir;
        uint4 uR, uG, uB;
        uR.x = q16(c[0].x) | (q16(c[1].x) << 16);
        uR.y = q16(c[2].x) | (q16(c[3].x) << 16);
        uR.z = q16(c[4].x) | (q16(c[5].x) << 16);
        uR.w = q16(c[6].x) | (q16(c[7].x) << 16);
        uG.x = q16(c[0].y) | (q16(c[1].y) << 16);
        uG.y = q16(c[2].y) | (q16(c[3].y) << 16);
        uG.z = q16(c[4].y) | (q16(c[5].y) << 16);
        uG.w = q16(c[6].y) | (q16(c[7].y) << 16);
        uB.x = q16(c[0].z) | (q16(c[1].z) << 16);
        uB.y = q16(c[2].z) | (q16(c[3].z) << 16);
        uB.z = q16(c[4].z) | (q16(c[5].z) << 16);
        uB.w = q16(c[6].z) | (q16(c[7].z) << 16);
        g_cube[cidx * 3 + 0] = uR;
        g_cube[cidx * 3 + 1] = uG;
        g_cube[cidx * 3 + 2] = uB;
    }
}

// ---------------------------------------------------------------------------
// Decoders
// ---------------------------------------------------------------------------
// 16-bit field + 2^23 exponent paste: one PRMT each.
__device__ __forceinline__ float d16lo(unsigned w) {
    return __uint_as_float(__byte_perm(w, EXPB, 0x7410));
}
__device__ __forceinline__ float d16hi(unsigned w) {
    return __uint_as_float(__byte_perm(w, EXPB, 0x7432));
}
__device__ __forceinline__ void decq(unsigned w,
                                     float& R, float& G, float& B) {
    R = __uint_as_float(EXPB | (w & 0x7FFu));
    G = __uint_as_float(EXPB | ((w >> 11) & 0x7FFu));
    B = __uint_as_float(EXPB | (w >> 22));
}

__device__ __forceinline__ void coords(float r, float g, float b,
                                       int& ir, int& ig, int& ib,
                                       float& fr, float& fg, float& fb) {
    r = fminf(fmaxf(r, 0.f), 1.f) * (float)(D - 1);
    g = fminf(fmaxf(g, 0.f), 1.f) * (float)(D - 1);
    b = fminf(fmaxf(b, 0.f), 1.f) * (float)(D - 1);
    ir = min((int)r, D - 2);
    ig = min((int)g, D - 2);
    ib = min((int)b, D - 2);
    fr = r - (float)ir;
    fg = g - (float)ig;
    fb = b - (float)ib;
}

// One channel from a cube record: trilinear over 8 biased corners.
__device__ __forceinline__ float cube_lerp(uint4 u, float fr, float fg, float fb) {
    float c0 = d16lo(u.x), c1 = d16hi(u.x);   // (dj=0,dk=0) r-pair
    float c2 = d16lo(u.y), c3 = d16hi(u.y);   // (dj=1,dk=0)
    float c4 = d16lo(u.z), c5 = d16hi(u.z);   // (dj=0,dk=1)
    float c6 = d16lo(u.w), c7 = d16hi(u.w);   // (dj=1,dk=1)
    float a0 = fmaf(fr, c1 - c0, c0);
    float a1 = fmaf(fr, c3 - c2, c2);
    float a2 = fmaf(fr, c5 - c4, c4);
    float a3 = fmaf(fr, c7 - c6, c6);
    float b0 = fmaf(fg, a1 - a0, a0);
    float b1 = fmaf(fg, a3 - a2, a2);
    return fmaf(fb, b1 - b0, b0);
}

// Stage 1: 3 x LDG.128 (R,G,B cube records for the cell).
__device__ __forceinline__ float3 lut3d_s1(float r, float g, float b) {
    int ir, ig, ib; float fr, fg, fb;
    coords(r, g, b, ir, ig, ib, fr, fg, fb);
    int cidx = ((ib * NC + ig) * NC + ir) * 3;

    uint4 uR = __ldg(g_cube + cidx);
    uint4 uG = __ldg(g_cube + cidx + 1);
    uint4 uB = __ldg(g_cube + cidx + 2);

    const float sc = 1.0f / Q16F;
    return make_float3((cube_lerp(uR, fr, fg, fb) - BIASF) * sc,
                       (cube_lerp(uG, fr, fg, fb) - BIASF) * sc,
                       (cube_lerp(uB, fr, fg, fb) - BIASF) * sc);
}

// Stage 2: 2 x LDG.128 ((r,g)-quad records, planes b and b+1).
__device__ __forceinline__ float3 lut3d_s2(float r, float g, float b) {
    int ir, ig, ib; float fr, fg, fb;
    coords(r, g, b, ir, ig, ib, fr, fg, fb);
    int idx = ib * DD + ig * D + ir;

    uint4 p0 = __ldg(g_pack2 + idx);
    uint4 p1 = __ldg(g_pack2 + idx + DD);

    float R00, G00, B00, R01, G01, B01, R10, G10, B10, R11, G11, B11;

    decq(p0.x, R00, G00, B00); decq(p0.y, R01, G01, B01);
    decq(p0.z, R10, G10, B10); decq(p0.w, R11, G11, B11);
    float r0x = fmaf(fr, R01 - R00, R00);
    float r0y = fmaf(fr, G01 - G00, G00);
    float r0z = fmaf(fr, B01 - B00, B00);
    float r1x = fmaf(fr, R11 - R10, R10);
    float r1y = fmaf(fr, G11 - G10, G10);
    float r1z = fmaf(fr, B11 - B10, B10);
    float p0x = fmaf(fg, r1x - r0x, r0x);
    float p0y = fmaf(fg, r1y - r0y, r0y);
    float p0z = fmaf(fg, r1z - r0z, r0z);

    decq(p1.x, R00, G00, B00); decq(p1.y, R01, G01, B01);
    decq(p1.z, R10, G10, B10); decq(p1.w, R11, G11, B11);
    r0x = fmaf(fr, R01 - R00, R00);
    r0y = fmaf(fr, G01 - G00, G00);
    r0z = fmaf(fr, B01 - B00, B00);
    r1x = fmaf(fr, R11 - R10, R10);
    r1y = fmaf(fr, G11 - G10, G10);
    r1z = fmaf(fr, B11 - B10, B10);
    float p1x = fmaf(fg, r1x - r0x, r0x);
    float p1y = fmaf(fg, r1y - r0y, r0y);
    float p1z = fmaf(fg, r1z - r0z, r0z);

    float tx = fmaf(fb, p1x - p0x, p0x);
    float ty = fmaf(fb, p1y - p0y, p0y);
    float tz = fmaf(fb, p1z - p0z, p0z);

    return make_float3((tx - BIASF) * (1.0f / Q11F),
                       (ty - BIASF) * (1.0f / Q11F),
                       (tz - BIASF) * (1.0f / Q10F));
}

// ---------------------------------------------------------------------------
// Kernel 3: fused dual-LUT application. 4 px/thread, float4 I/O, 256-thr blocks.
// ---------------------------------------------------------------------------
#define PIX_PER_THREAD 4

__global__ __launch_bounds__(256)
void apply_lut_kernel(const float* __restrict__ gt,
                      float* __restrict__ out, int hw) {
    int t = blockIdx.x * blockDim.x + threadIdx.x;
    int base = t * PIX_PER_THREAD;
    if (base >= hw) return;

    const float4 r4 = *reinterpret_cast<const float4*>(gt + base);
    const float4 g4 = *reinterpret_cast<const float4*>(gt + hw + base);
    const float4 b4 = *reinterpret_cast<const float4*>(gt + 2 * hw + base);

    float ri[4] = {r4.x, r4.y, r4.z, r4.w};
    float gi[4] = {g4.x, g4.y, g4.z, g4.w};
    float bi[4] = {b4.x, b4.y, b4.z, b4.w};
    float ro[4], go[4], bo[4];

    #pragma unroll
    for (int p = 0; p < PIX_PER_THREAD; p++) {
        float3 s = lut3d_s1(ri[p], gi[p], bi[p]);
        float3 f = lut3d_s2(s.x, s.y, s.z);
        ro[p] = f.x; go[p] = f.y; bo[p] = f.z;
    }

    *reinterpret_cast<float4*>(out + base)          = make_float4(ro[0], ro[1], ro[2], ro[3]);
    *reinterpret_cast<float4*>(out + hw + base)     = make_float4(go[0], go[1], go[2], go[3]);
    *reinterpret_cast<float4*>(out + 2 * hw + base) = make_float4(bo[0], bo[1], bo[2], bo[3]);
}

// ---------------------------------------------------------------------------
extern "C" void kernel_launch(void* const* d_in, const int* in_sizes, int n_in,
                              void* d_out, int out_size) {
    const float* gt  = (const float*)d_in[0];   // [3, 2160, 3840]
    const float* lut = (const float*)d_in[1];   // [2, 8, 3, 33, 33, 33]
    const float* lc0 = (const float*)d_in[2];   // [8]
    const float* lc1 = (const float*)d_in[3];   // [8]
    float* out = (float*)d_out;

    const int hw = in_sizes[0] / 3;             // 8294400

    {
        int threads = 256;
        int blocks  = (2 * NL + threads - 1) / threads;
        build_clut_kernel<<<blocks, threads>>>(lut, lc0, lc1);
    }
    {
        int threads = 256;
        int blocks  = (NL + threads - 1) / threads;
        pack_clut_kernel<<<blocks, threads>>>();
    }
    {
        int threads = 256;
        int total_threads = hw / PIX_PER_THREAD;
        int blocks = (total_threads + threads - 1) / threads;
        apply_lut_kernel<<<blocks, threads>>>(gt, out, hw);
    }
}